// round 4
// baseline (speedup 1.0000x reference)
#include <cuda_runtime.h>
#include <math_constants.h>

// Problem constants
#define T_LEN   4096
#define BATCH   32
#define DMODEL  256
#define NSTATE  64
#define NPAIRS  (BATCH * DMODEL)   // 8192 (b,d) pairs
#define NWIN    (T_LEN / 8)        // 512 windows of 8 timesteps

// pooled[b][0:256]=avg, pooled[b][256:512]=max
__device__ float g_pooled[BATCH * 2 * DMODEL];

using ull = unsigned long long;

// ---- f32x2 helpers (sm_100+ packed fp32: 2x FMA throughput per instr) ----
__device__ __forceinline__ ull pack2(float lo, float hi) {
    ull r; asm("mov.b64 %0, {%1, %2};" : "=l"(r) : "f"(lo), "f"(hi)); return r;
}
__device__ __forceinline__ ull bcast2(float x) {
    ull r; asm("mov.b64 %0, {%1, %1};" : "=l"(r) : "f"(x)); return r;
}
__device__ __forceinline__ ull fma2(ull a, ull b, ull c) {
    ull r; asm("fma.rn.f32x2 %0, %1, %2, %3;" : "=l"(r) : "l"(a), "l"(b), "l"(c)); return r;
}
__device__ __forceinline__ ull mul2(ull a, ull b) {
    ull r; asm("mul.rn.f32x2 %0, %1, %2;" : "=l"(r) : "l"(a), "l"(b)); return r;
}
__device__ __forceinline__ ull add2(ull a, ull b) {
    ull r; asm("add.rn.f32x2 %0, %1, %2;" : "=l"(r) : "l"(a), "l"(b)); return r;
}
__device__ __forceinline__ float2 unpack2(ull a) {
    float2 f; asm("mov.b64 {%0, %1}, %2;" : "=f"(f.x), "=f"(f.y) : "l"(a)); return f;
}
__device__ __forceinline__ ull shfl64(ull v, int m) {
    return __shfl_xor_sync(0xffffffffu, v, m);
}

// tanh-approx gelu matching jax.nn.gelu (approximate=True, the default)
__device__ __forceinline__ float gelu_tanh(float y) {
    float y2 = y * y;
    float inner = 0.7978845608028654f * y * fmaf(0.044715f, y2, 1.0f);
    float e = __expf(2.0f * inner);                 // MUFU path
    float r = __fdividef(1.0f, 1.0f + e);           // (1-tanh)/2
    return y - y * r;                               // 0.5*y*(1+tanh)
}

// One warp = 4 (b,d) pairs. Each pair owned by 8 lanes; each lane holds 8
// states as 4 f32x2 registers. Rescaled recurrence v' = a*v' + u with
// cb = B.*C so y_ssm = dot(cb, v'). Per 8-step window: packed per-timestep
// partial sums pt0..pt7, then a 3-round packed reduce-scatter lands each
// lane its own timestep's full sum -> gelu/pool amortized 1-per-8-steps.
__global__ void __launch_bounds__(32)
ssm_scan_kernel(const float* __restrict__ x,
                const float* __restrict__ w_in,
                const float* __restrict__ b_in,
                const float* __restrict__ A_diag,
                const float* __restrict__ B_in,
                const float* __restrict__ C_out,
                const float* __restrict__ D_skip)
{
    const int lane = threadIdx.x;            // 0..31
    const int o    = lane & 7;               // lane within pair-group
    const int g    = lane >> 3;              // pair-group within warp (0..3)
    const int p    = blockIdx.x * 4 + g;     // (b,d) pair id, 0..8191
    const int b    = p >> 8;
    const int d    = p & 255;

    const bool o1 = (o & 1) != 0;
    const bool o2 = (o & 2) != 0;
    const bool o4 = (o & 4) != 0;

    const float wd  = w_in[d];
    const float bd  = b_in[d];
    const float dsk = D_skip[d];

    ull a2_0, a2_1, a2_2, a2_3;
    ull cb_0, cb_1, cb_2, cb_3;
    ull v2_0 = 0, v2_1 = 0, v2_2 = 0, v2_3 = 0;
    {
        const int base = d * NSTATE + o * 8;
        const float4* A4 = reinterpret_cast<const float4*>(A_diag + base);
        const float4* B4 = reinterpret_cast<const float4*>(B_in  + base);
        const float4* C4 = reinterpret_cast<const float4*>(C_out + base);
        float4 Aa = A4[0], Ab = A4[1];
        float4 Ba = B4[0], Bb = B4[1];
        float4 Ca = C4[0], Cb = C4[1];
        a2_0 = pack2(Aa.x, Aa.y);  a2_1 = pack2(Aa.z, Aa.w);
        a2_2 = pack2(Ab.x, Ab.y);  a2_3 = pack2(Ab.z, Ab.w);
        cb_0 = pack2(Ba.x * Ca.x, Ba.y * Ca.y);
        cb_1 = pack2(Ba.z * Ca.z, Ba.w * Ca.w);
        cb_2 = pack2(Bb.x * Cb.x, Bb.y * Cb.y);
        cb_3 = pack2(Bb.z * Cb.z, Bb.w * Cb.w);
    }

    float asum = 0.0f;
    float amax = -CUDART_INF_F;

    const float4* xb4 = reinterpret_cast<const float4*>(x + b * T_LEN);

    // prefetch window 0
    float4 nx0 = __ldg(&xb4[0]);
    float4 nx1 = __ldg(&xb4[1]);

    #define WINDOW_BODY(PREFETCH_STMT)                                         \
    {                                                                          \
        float4 x0 = nx0, x1 = nx1;                                             \
        PREFETCH_STMT                                                          \
        ull pt0, pt1, pt2r, pt3, pt4, pt5, pt6, pt7;                           \
        /* 8 recurrence steps, packed partial sums */                          \
        STEP(pt0, x0.x)  STEP(pt1, x0.y)  STEP(pt2r, x0.z)  STEP(pt3, x0.w)    \
        STEP(pt4, x1.x)  STEP(pt5, x1.y)  STEP(pt6,  x1.z)  STEP(pt7, x1.w)    \
        /* 3-round packed reduce-scatter over the 8-lane group */              \
        ull k, s;                                                              \
        k = o4 ? pt4 : pt0;  s = o4 ? pt0 : pt4;  ull q10 = add2(k, shfl64(s, 4)); \
        k = o4 ? pt5 : pt1;  s = o4 ? pt1 : pt5;  ull q11 = add2(k, shfl64(s, 4)); \
        k = o4 ? pt6 : pt2r; s = o4 ? pt2r : pt6; ull q12 = add2(k, shfl64(s, 4)); \
        k = o4 ? pt7 : pt3;  s = o4 ? pt3 : pt7;  ull q13 = add2(k, shfl64(s, 4)); \
        k = o2 ? q12 : q10;  s = o2 ? q10 : q12;  ull q20 = add2(k, shfl64(s, 2)); \
        k = o2 ? q13 : q11;  s = o2 ? q11 : q13;  ull q21 = add2(k, shfl64(s, 2)); \
        k = o1 ? q21 : q20;  s = o1 ? q20 : q21;  ull q3  = add2(k, shfl64(s, 1)); \
        float2 pf = unpack2(q3);                                               \
        float ps = pf.x + pf.y;                                                \
        /* recover this lane's own u via 3-level mux of the window's x */      \
        float xa = o1 ? x0.y : x0.x;                                           \
        float xb = o1 ? x0.w : x0.z;                                           \
        float xc = o1 ? x1.y : x1.x;                                           \
        float xd = o1 ? x1.w : x1.z;                                           \
        float xe = o2 ? xb : xa;                                               \
        float xf = o2 ? xd : xc;                                               \
        float xo = o4 ? xf : xe;                                               \
        float uo = fmaf(xo, wd, bd);                                           \
        float y = fmaf(dsk, uo, ps);                                           \
        float h = gelu_tanh(y);                                                \
        asum += h;                                                             \
        amax = fmaxf(amax, h);                                                 \
    }

    #define STEP(PT, XV)                                   \
    {                                                      \
        float u_ = fmaf((XV), wd, bd);                     \
        ull u2_ = bcast2(u_);                              \
        v2_0 = fma2(a2_0, v2_0, u2_);                      \
        v2_1 = fma2(a2_1, v2_1, u2_);                      \
        v2_2 = fma2(a2_2, v2_2, u2_);                      \
        v2_3 = fma2(a2_3, v2_3, u2_);                      \
        ull t_ = mul2(cb_0, v2_0);                         \
        t_ = fma2(cb_1, v2_1, t_);                         \
        t_ = fma2(cb_2, v2_2, t_);                         \
        t_ = fma2(cb_3, v2_3, t_);                         \
        PT = t_;                                           \
    }

    // main loop: prefetch next window unconditionally (w+1 always valid)
    for (int w = 0; w < NWIN - 1; w++) {
        WINDOW_BODY(
            nx0 = __ldg(&xb4[2 * (w + 1)]);
            nx1 = __ldg(&xb4[2 * (w + 1) + 1]);
        )
    }
    // peeled last window: no prefetch
    WINDOW_BODY()

    #undef STEP
    #undef WINDOW_BODY

    // combine the 8 lanes' phase-partial accumulators
    asum += __shfl_xor_sync(0xffffffffu, asum, 1);
    asum += __shfl_xor_sync(0xffffffffu, asum, 2);
    asum += __shfl_xor_sync(0xffffffffu, asum, 4);
    amax = fmaxf(amax, __shfl_xor_sync(0xffffffffu, amax, 1));
    amax = fmaxf(amax, __shfl_xor_sync(0xffffffffu, amax, 2));
    amax = fmaxf(amax, __shfl_xor_sync(0xffffffffu, amax, 4));

    if (o == 0) {
        g_pooled[b * (2 * DMODEL) + d]          = asum * (1.0f / T_LEN);
        g_pooled[b * (2 * DMODEL) + DMODEL + d] = amax;
    }
}

// one warp per (b, class): dot(pooled[b,:512], W_head[:,c]) + b_head[c]
__global__ void __launch_bounds__(32)
head_kernel(const float* __restrict__ W_head,
            const float* __restrict__ b_head,
            float* __restrict__ out)
{
    const int b = blockIdx.x / 5;
    const int c = blockIdx.x % 5;
    const int lane = threadIdx.x;

    float p = 0.0f;
    const float* pb = g_pooled + b * (2 * DMODEL);
    #pragma unroll 4
    for (int k = lane; k < 2 * DMODEL; k += 32)
        p += pb[k] * W_head[k * 5 + c];

    #pragma unroll
    for (int m = 16; m >= 1; m >>= 1)
        p += __shfl_xor_sync(0xffffffffu, p, m);

    if (lane == 0) out[b * 5 + c] = p + b_head[c];
}

extern "C" void kernel_launch(void* const* d_in, const int* in_sizes, int n_in,
                              void* d_out, int out_size)
{
    const float* x      = (const float*)d_in[0];  // [32, 4096]
    const float* w_in   = (const float*)d_in[1];  // [256]
    const float* b_in   = (const float*)d_in[2];  // [256]
    const float* A_diag = (const float*)d_in[3];  // [256, 64]
    const float* B_in   = (const float*)d_in[4];  // [256, 64]
    const float* C_out  = (const float*)d_in[5];  // [256, 64]
    const float* D_skip = (const float*)d_in[6];  // [256]
    const float* W_head = (const float*)d_in[7];  // [512, 5]
    const float* b_head = (const float*)d_in[8];  // [5]
    float* out = (float*)d_out;                   // [32, 5]

    ssm_scan_kernel<<<NPAIRS / 4, 32>>>(x, w_in, b_in, A_diag, B_in, C_out, D_skip);
    head_kernel<<<BATCH * 5, 32>>>(W_head, b_head, out);
}

// round 16
// speedup vs baseline: 1.3167x; 1.3167x over previous
#include <cuda_runtime.h>
#include <math_constants.h>

// Problem constants
#define T_LEN   4096
#define BATCH   32
#define DMODEL  256
#define NSTATE  64
#define NWIN    (T_LEN / 8)        // 512 windows of 8 timesteps (2 groups of 4)

// pooled[b][0:256]=avg, pooled[b][256:512]=max
__device__ float g_pooled[BATCH * 2 * DMODEL];

using ull = unsigned long long;

// ---- f32x2 helpers (sm_100+ packed fp32) ----
__device__ __forceinline__ ull pack2(float lo, float hi) {
    ull r; asm("mov.b64 %0, {%1, %2};" : "=l"(r) : "f"(lo), "f"(hi)); return r;
}
__device__ __forceinline__ ull bcast2(float x) {
    ull r; asm("mov.b64 %0, {%1, %1};" : "=l"(r) : "f"(x)); return r;
}
__device__ __forceinline__ ull fma2(ull a, ull b, ull c) {
    ull r; asm("fma.rn.f32x2 %0, %1, %2, %3;" : "=l"(r) : "l"(a), "l"(b), "l"(c)); return r;
}
__device__ __forceinline__ ull mul2(ull a, ull b) {
    ull r; asm("mul.rn.f32x2 %0, %1, %2;" : "=l"(r) : "l"(a), "l"(b)); return r;
}
__device__ __forceinline__ ull add2(ull a, ull b) {
    ull r; asm("add.rn.f32x2 %0, %1, %2;" : "=l"(r) : "l"(a), "l"(b)); return r;
}
__device__ __forceinline__ float2 unpack2(ull a) {
    float2 f; asm("mov.b64 {%0, %1}, %2;" : "=f"(f.x), "=f"(f.y) : "l"(a)); return f;
}

// tanh-approx gelu matching jax.nn.gelu (approximate=True, the default)
__device__ __forceinline__ float gelu_tanh(float y) {
    float y2 = y * y;
    float inner = 0.7978845608028654f * y * fmaf(0.044715f, y2, 1.0f);
    float e = __expf(2.0f * inner);
    float r = __fdividef(1.0f, 1.0f + e);
    return y - y * r;
}

// Layout (same as the 275us R1 kernel): 64-thread block = 16 (b,d) pairs.
// Each pair owned by 4 lanes (q = lane&3); each lane holds 16 states as
// 8 f32x2 regs. Rescaled recurrence v' = a*v' + u, y_ssm = dot(cb, v'),
// cb = B.*C.
//
// The cross-lane reduce + gelu runs as a 3-stage software pipeline at
// 4-step-group granularity:
//   group g   : v-updates + per-lane tree folds -> ps0..ps3 (scalar)
//   StageA(g-1): SHFL xor2 round  -> m0,m1
//   StageB(g-2): SHFL xor1 round  -> f  (lane q holds full sum of its step)
//   StageC(g-3): y = dsk*u + f, gelu, avg/max pool
// Every consumer's producer is >=1 group (~110 issue slots) old, so the
// 26-cycle SHFL latency and the gelu chain never block in-order issue.
__global__ void __launch_bounds__(64)
ssm_scan_kernel(const float* __restrict__ x,
                const float* __restrict__ w_in,
                const float* __restrict__ b_in,
                const float* __restrict__ A_diag,
                const float* __restrict__ B_in,
                const float* __restrict__ C_out,
                const float* __restrict__ D_skip)
{
    const int tid = threadIdx.x;                 // 0..63
    const int b   = blockIdx.x >> 4;             // 512 blocks: 16 per batch row
    const int d   = ((blockIdx.x & 15) << 4) + (tid >> 2);
    const int q   = tid & 3;                     // lane within pair-group

    const bool q1 = (q & 1) != 0;
    const bool q2 = (q & 2) != 0;

    const float wd  = w_in[d];
    const float bd  = b_in[d];
    const float dsk = D_skip[d];

    ull a2_0, a2_1, a2_2, a2_3, a2_4, a2_5, a2_6, a2_7;
    ull cb_0, cb_1, cb_2, cb_3, cb_4, cb_5, cb_6, cb_7;
    ull v2_0 = 0, v2_1 = 0, v2_2 = 0, v2_3 = 0;
    ull v2_4 = 0, v2_5 = 0, v2_6 = 0, v2_7 = 0;
    {
        const int base = d * NSTATE + q * 16;
        const float4* A4 = reinterpret_cast<const float4*>(A_diag + base);
        const float4* B4 = reinterpret_cast<const float4*>(B_in  + base);
        const float4* C4 = reinterpret_cast<const float4*>(C_out + base);
        #pragma unroll
        for (int i = 0; i < 4; i++) {
            float4 Aa = A4[i], Ba = B4[i], Ca = C4[i];
            ull av = pack2(Aa.x, Aa.y), aw = pack2(Aa.z, Aa.w);
            ull cv = pack2(Ba.x * Ca.x, Ba.y * Ca.y);
            ull cw = pack2(Ba.z * Ca.z, Ba.w * Ca.w);
            if (i == 0) { a2_0 = av; a2_1 = aw; cb_0 = cv; cb_1 = cw; }
            if (i == 1) { a2_2 = av; a2_3 = aw; cb_2 = cv; cb_3 = cw; }
            if (i == 2) { a2_4 = av; a2_5 = aw; cb_4 = cv; cb_5 = cw; }
            if (i == 3) { a2_6 = av; a2_7 = aw; cb_6 = cv; cb_7 = cw; }
        }
    }

    float asum = 0.0f;
    float amax = -CUDART_INF_F;

    // pipeline state
    float ps0, ps1, ps2, ps3;          // current group's per-lane tree folds
    float aps0 = 0, aps1 = 0, aps2 = 0, aps3 = 0;  // group g-1
    float m0 = 0, m1 = 0;              // group g-2 (after SHFL xor2)
    float f  = 0;                      // group g-3 (full sum for own step)
    float uo = 0, u1 = 0, u2 = 0, u3 = 0;  // u history for own-phase steps

    const float4* xb4 = reinterpret_cast<const float4*>(x + b * T_LEN);

    // prefetch window 0
    float4 nx0 = __ldg(&xb4[0]);
    float4 nx1 = __ldg(&xb4[1]);
    float4 x0, x1;

    // one recurrence step + reduction tree fold -> scalar PSLOT
    #define TREESTEP(PSLOT, XV)                                    \
    {                                                              \
        float u_ = fmaf((XV), wd, bd);                             \
        ull u2_ = bcast2(u_);                                      \
        v2_0 = fma2(a2_0, v2_0, u2_);                              \
        v2_1 = fma2(a2_1, v2_1, u2_);                              \
        v2_2 = fma2(a2_2, v2_2, u2_);                              \
        v2_3 = fma2(a2_3, v2_3, u2_);                              \
        v2_4 = fma2(a2_4, v2_4, u2_);                              \
        v2_5 = fma2(a2_5, v2_5, u2_);                              \
        v2_6 = fma2(a2_6, v2_6, u2_);                              \
        v2_7 = fma2(a2_7, v2_7, u2_);                              \
        ull p0_ = mul2(cb_0, v2_0);                                \
        ull p1_ = mul2(cb_1, v2_1);                                \
        p0_ = fma2(cb_2, v2_2, p0_);                               \
        p1_ = fma2(cb_3, v2_3, p1_);                               \
        p0_ = fma2(cb_4, v2_4, p0_);                               \
        p1_ = fma2(cb_5, v2_5, p1_);                               \
        p0_ = fma2(cb_6, v2_6, p0_);                               \
        p1_ = fma2(cb_7, v2_7, p1_);                               \
        float2 pf_ = unpack2(add2(p0_, p1_));                      \
        PSLOT = pf_.x + pf_.y;                                     \
    }

    // group core: 4 steps + own-phase u for this group
    #define GROUP_CORE(X4)                                         \
    {                                                              \
        TREESTEP(ps0, (X4).x)                                      \
        TREESTEP(ps1, (X4).y)                                      \
        TREESTEP(ps2, (X4).z)                                      \
        TREESTEP(ps3, (X4).w)                                      \
        float xa_ = q1 ? (X4).y : (X4).x;                          \
        float xb_ = q1 ? (X4).w : (X4).z;                          \
        float xo_ = q2 ? xb_ : xa_;                                \
        uo = fmaf(xo_, wd, bd);                                    \
    }

    // StageA on aps (group g-1): SHFL xor2 round
    #define STAGE_A                                                \
    {                                                              \
        float ka_ = q2 ? aps2 : aps0, sa_ = q2 ? aps0 : aps2;      \
        float kb_ = q2 ? aps3 : aps1, sb_ = q2 ? aps1 : aps3;      \
        m0 = ka_ + __shfl_xor_sync(0xffffffffu, sa_, 2);           \
        m1 = kb_ + __shfl_xor_sync(0xffffffffu, sb_, 2);           \
    }

    // StageB on m (group g-2): SHFL xor1 round -> f
    #define STAGE_B                                                \
    {                                                              \
        float kc_ = q1 ? m1 : m0, sc_ = q1 ? m0 : m1;              \
        f = kc_ + __shfl_xor_sync(0xffffffffu, sc_, 1);            \
    }

    // StageC (group g-3): finish own step
    #define STAGE_C(FV, UV)                                        \
    {                                                              \
        float y_ = fmaf(dsk, (UV), (FV));                          \
        float h_ = gelu_tanh(y_);                                  \
        asum += h_;                                                \
        amax = fmaxf(amax, h_);                                    \
    }

    #define SHIFT  { aps0 = ps0; aps1 = ps1; aps2 = ps2; aps3 = ps3; \
                     u3 = u2; u2 = u1; u1 = uo; }

    #define STEADY(X4)  { GROUP_CORE(X4) STAGE_C(f, u3) STAGE_B STAGE_A SHIFT }

    // ---- prologue: window 0 (groups 0,1) ----
    x0 = nx0; x1 = nx1;
    nx0 = __ldg(&xb4[2]); nx1 = __ldg(&xb4[3]);
    GROUP_CORE(x0)                         // g0
    SHIFT
    GROUP_CORE(x1)                         // g1
    STAGE_A                                // m = m(g0)
    SHIFT
    // ---- window 1 (groups 2,3) ----
    x0 = nx0; x1 = nx1;
    nx0 = __ldg(&xb4[4]); nx1 = __ldg(&xb4[5]);
    GROUP_CORE(x0)                         // g2
    STAGE_B                                // f = f(g0)
    STAGE_A                                // m = m(g1)
    SHIFT
    STEADY(x1)                             // g3 (first full pipeline group)

    // ---- main loop: windows 2..NWIN-2, unconditional prefetch ----
    for (int w = 2; w < NWIN - 1; w++) {
        x0 = nx0; x1 = nx1;
        nx0 = __ldg(&xb4[2 * (w + 1)]);
        nx1 = __ldg(&xb4[2 * (w + 1) + 1]);
        STEADY(x0)
        STEADY(x1)
    }
    // ---- last window (no prefetch) ----
    x0 = nx0; x1 = nx1;
    STEADY(x0)
    STEADY(x1)

    // ---- epilogue drain: groups N-3, N-2, N-1 ----
    STAGE_C(f, u3)    // group N-3
    STAGE_B           // f = f(N-2)
    STAGE_C(f, u2)    // group N-2
    STAGE_A           // m = m(N-1)
    STAGE_B           // f = f(N-1)
    STAGE_C(f, u1)    // group N-1

    #undef TREESTEP
    #undef GROUP_CORE
    #undef STAGE_A
    #undef STAGE_B
    #undef STAGE_C
    #undef SHIFT
    #undef STEADY

    // combine the 4 lanes' phase-partial accumulators
    asum += __shfl_xor_sync(0xffffffffu, asum, 1);
    asum += __shfl_xor_sync(0xffffffffu, asum, 2);
    amax = fmaxf(amax, __shfl_xor_sync(0xffffffffu, amax, 1));
    amax = fmaxf(amax, __shfl_xor_sync(0xffffffffu, amax, 2));

    if (q == 0) {
        g_pooled[b * (2 * DMODEL) + d]          = asum * (1.0f / T_LEN);
        g_pooled[b * (2 * DMODEL) + DMODEL + d] = amax;
    }
}

// one warp per (b, class): dot(pooled[b,:512], W_head[:,c]) + b_head[c]
__global__ void __launch_bounds__(32)
head_kernel(const float* __restrict__ W_head,
            const float* __restrict__ b_head,
            float* __restrict__ out)
{
    const int b = blockIdx.x / 5;
    const int c = blockIdx.x % 5;
    const int lane = threadIdx.x;

    float p = 0.0f;
    const float* pb = g_pooled + b * (2 * DMODEL);
    #pragma unroll 4
    for (int k = lane; k < 2 * DMODEL; k += 32)
        p += pb[k] * W_head[k * 5 + c];

    #pragma unroll
    for (int m = 16; m >= 1; m >>= 1)
        p += __shfl_xor_sync(0xffffffffu, p, m);

    if (lane == 0) out[b * 5 + c] = p + b_head[c];
}

extern "C" void kernel_launch(void* const* d_in, const int* in_sizes, int n_in,
                              void* d_out, int out_size)
{
    const float* x      = (const float*)d_in[0];  // [32, 4096]
    const float* w_in   = (const float*)d_in[1];  // [256]
    const float* b_in   = (const float*)d_in[2];  // [256]
    const float* A_diag = (const float*)d_in[3];  // [256, 64]
    const float* B_in   = (const float*)d_in[4];  // [256, 64]
    const float* C_out  = (const float*)d_in[5];  // [256, 64]
    const float* D_skip = (const float*)d_in[6];  // [256]
    const float* W_head = (const float*)d_in[7];  // [512, 5]
    const float* b_head = (const float*)d_in[8];  // [5]
    float* out = (float*)d_out;                   // [32, 5]

    ssm_scan_kernel<<<512, 64>>>(x, w_in, b_in, A_diag, B_in, C_out, D_skip);
    head_kernel<<<BATCH * 5, 32>>>(W_head, b_head, out);
}